// round 5
// baseline (speedup 1.0000x reference)
#include <cuda_runtime.h>
#include <cuda_fp16.h>
#include <math.h>

#define NN 100000
#define EE 1600000
#define HID 64
#define KORD 14
#define HEADS 8
#define NGRAPH 128
#define NCLS 10

// ---------------- scratch (device globals; no runtime alloc) ----------------
// Chebyshev T buffers: int8 features (16 ints = 64 bytes per node) + per-node half scale
__device__ int    g_q0[NN * 16];
__device__ int    g_q1[NN * 16];
__device__ int    g_q2[NN * 16];
__device__ __half g_s0[NN];
__device__ __half g_s1[NN];
__device__ __half g_s2[NN];
__device__ __half g_outh[NN * HID];   // half accumulator of sum_k c_k T_k
__device__ float  g_h   [NN * HID];   // fp32 layer output (GEMM input / pool input)
__device__ int    g_deg[NN];
__device__ float  g_dinv[NN];
__device__ int    g_rowptr[NN + 1];
__device__ int    g_cursor[NN];
__device__ int2   g_edge[EE];         // {col, float_bits(weight)}
__device__ float  g_coeff[3][KORD];

// ---------------- init: zero deg + cursor ----------------
__global__ void init_kernel() {
    int i = blockIdx.x * blockDim.x + threadIdx.x;
    if (i < NN) { g_deg[i] = 0; g_cursor[i] = 0; }
}

__global__ void count_deg_kernel(const int* __restrict__ row) {
    int e = blockIdx.x * blockDim.x + threadIdx.x;
    if (e < EE) atomicAdd(&g_deg[row[e]], 1);
}

// scan + dinv + coeff fused (single block)
__global__ void scan_kernel(const float* __restrict__ theta1,
                            const float* __restrict__ thetas) {
    __shared__ int sums[1024];
    const int T = 1024;
    int tid = threadIdx.x;

    if (tid < 3 * KORD) {
        int layer = tid / KORD, k = tid % KORD;
        const float* th = (layer == 0) ? theta1 : thetas + (layer - 1) * HEADS * KORD;
        float s = 0.f;
        for (int h = 0; h < HEADS; h++) s += th[h * KORD + k];
        g_coeff[layer][k] = s * (1.0f / HEADS);
    }

    int per = (NN + T - 1) / T;
    int start = tid * per;
    int end = start + per; if (end > NN) end = NN;
    int local = 0;
    for (int i = start; i < end; i++) local += g_deg[i];
    sums[tid] = local;
    __syncthreads();
    for (int off = 1; off < T; off <<= 1) {
        int t = (tid >= off) ? sums[tid - off] : 0;
        __syncthreads();
        sums[tid] += t;
        __syncthreads();
    }
    int excl = sums[tid] - local;
    int run = excl;
    for (int i = start; i < end; i++) {
        int d = g_deg[i];
        g_rowptr[i] = run; run += d;
        g_dinv[i] = rsqrtf(fmaxf((float)d, 1.0f));
    }
    if (tid == T - 1) g_rowptr[NN] = run;
}

__global__ void scatter_kernel(const int* __restrict__ row, const int* __restrict__ col) {
    int e = blockIdx.x * blockDim.x + threadIdx.x;
    if (e < EE) {
        int r = row[e], c = col[e];
        int pos = g_rowptr[r] + atomicAdd(&g_cursor[r], 1);
        float w = -g_dinv[r] * g_dinv[c];
        g_edge[pos] = make_int2(c, __float_as_int(w));
    }
}

// ---------------- quantization helpers ----------------
// 16-lane segment reduce of row max, then pack 4 features to int8x4.
__device__ __forceinline__ void quant_store(float4 v, int* __restrict__ qb,
                                            __half* __restrict__ sb,
                                            int row, int sub, unsigned mask) {
    float m = fmaxf(fmaxf(fabsf(v.x), fabsf(v.y)), fmaxf(fabsf(v.z), fabsf(v.w)));
#pragma unroll
    for (int off = 8; off; off >>= 1) m = fmaxf(m, __shfl_xor_sync(mask, m, off, 16));
    float inv = (m > 0.f) ? 127.f / m : 0.f;
    int qx = __float2int_rn(v.x * inv);
    int qy = __float2int_rn(v.y * inv);
    int qz = __float2int_rn(v.z * inv);
    int qw = __float2int_rn(v.w * inv);
    int pk = (qx & 255) | ((qy & 255) << 8) | ((qz & 255) << 16) | (qw << 24);
    qb[(size_t)row * 16 + sub] = pk;
    if (sub == 0) sb[row] = __float2half(m * (1.f / 127.f));
}

__device__ __forceinline__ float4 dequant4(int qv, float sc) {
    return make_float4(sc * (float)(char)(qv),
                       sc * (float)(char)(qv >> 8),
                       sc * (float)(char)(qv >> 16),
                       sc * (float)(qv >> 24));
}

// ---------------- GEMM: Y[N][64] = A[N][FIN] @ W[FIN][64]  (int8+scale output) ----------------
template <int FIN>
__global__ __launch_bounds__(256) void gemm_kernel(const float* __restrict__ A,
                                                   const float* __restrict__ W,
                                                   int* __restrict__ Yq,
                                                   __half* __restrict__ Ys) {
    __shared__ float As[64][68];
    __shared__ float Ws[64][64];
    int rowbase = blockIdx.x * 64;
    int tid = threadIdx.x;
    int tx = tid & 15;
    int ty = tid >> 4;
    float acc[4][4];
#pragma unroll
    for (int i = 0; i < 4; i++)
#pragma unroll
        for (int j = 0; j < 4; j++) acc[i][j] = 0.f;

    for (int kk = 0; kk < FIN; kk += 64) {
#pragma unroll
        for (int j = 0; j < 4; j++) {
            int idx = tid + j * 256;
            int r = idx >> 4;
            int kq = idx & 15;
            float4 v = make_float4(0.f, 0.f, 0.f, 0.f);
            int gr = rowbase + r;
            if (gr < NN) v = *(const float4*)(A + (size_t)gr * FIN + kk + kq * 4);
            As[kq * 4 + 0][r] = v.x;
            As[kq * 4 + 1][r] = v.y;
            As[kq * 4 + 2][r] = v.z;
            As[kq * 4 + 3][r] = v.w;
        }
#pragma unroll
        for (int j = 0; j < 4; j++) {
            int idx = tid + j * 256;
            int k = idx >> 4;
            int fq = idx & 15;
            *(float4*)&Ws[k][fq * 4] = *(const float4*)(W + (size_t)(kk + k) * 64 + fq * 4);
        }
        __syncthreads();
#pragma unroll
        for (int k = 0; k < 64; k++) {
            float4 a = *(const float4*)&As[k][ty * 4];
            float4 b = *(const float4*)&Ws[k][tx * 4];
            float ar[4] = {a.x, a.y, a.z, a.w};
            float br[4] = {b.x, b.y, b.z, b.w};
#pragma unroll
            for (int i = 0; i < 4; i++)
#pragma unroll
                for (int j = 0; j < 4; j++) acc[i][j] += ar[i] * br[j];
        }
        __syncthreads();
    }
    // quantized epilogue: row max over the 16 tx lanes per row
#pragma unroll
    for (int i = 0; i < 4; i++) {
        int r = rowbase + ty * 4 + i;
        float4 v = make_float4(acc[i][0], acc[i][1], acc[i][2], acc[i][3]);
        if (r < NN) quant_store(v, Yq, Ys, r, tx, 0xffffffffu);
        else {  // keep shuffles uniform (all lanes of the 16-group share validity anyway)
            float m = 0.f;
#pragma unroll
            for (int off = 8; off; off >>= 1) m = fmaxf(m, __shfl_xor_sync(0xffffffffu, m, off, 16));
        }
    }
}

// ---------------- int8 Chebyshev propagation: half-warp per row, 4 features/lane ----------------
__device__ __forceinline__ float4 prop_row4_q(const int* __restrict__ q,
                                              const __half* __restrict__ s,
                                              int st, int en, int sub, unsigned mask) {
    float ax = 0.f, ay = 0.f, az = 0.f, aw = 0.f;
    const int* qp = q + sub;
    for (int base = st; base < en; base += 16) {
        int idx = base + sub;
        int2 ew = make_int2(0, 0);
        if (idx < en) ew = __ldg(&g_edge[idx]);
        int cnt = en - base;
        int qraw[16];
        float scv[16];
#pragma unroll
        for (int j = 0; j < 16; j++) {
            int cj = __shfl_sync(mask, ew.x, j, 16);
            qraw[j] = 0; scv[j] = 0.f;
            if (j < cnt) {
                qraw[j] = __ldg(&qp[(size_t)cj * 16]);
                scv[j] = __half2float(__ldg(&s[cj]));   // 200KB array: L1-resident
            }
        }
#pragma unroll
        for (int j = 0; j < 16; j++) {
            float wj = __int_as_float(__shfl_sync(mask, ew.y, j, 16));
            float w = wj * scv[j];
            int qv = qraw[j];
            ax += w * (float)(char)(qv);
            ay += w * (float)(char)(qv >> 8);
            az += w * (float)(char)(qv >> 16);
            aw += w * (float)(qv >> 24);
        }
    }
    return make_float4(ax, ay, az, aw);
}

__device__ __forceinline__ int2 pack4h(float a, float b, float c, float d) {
    __half2 h0 = __floats2half2_rn(a, b);
    __half2 h1 = __floats2half2_rn(c, d);
    int2 r;
    r.x = *(int*)&h0;
    r.y = *(int*)&h1;
    return r;
}

__device__ __forceinline__ float4 unpack4h(int2 raw) {
    float2 f0 = __half22float2(*(__half2*)&raw.x);
    float2 f1 = __half22float2(*(__half2*)&raw.y);
    return make_float4(f0.x, f0.y, f1.x, f1.y);
}

// first: t_cur = L~ y ; out = c0*y + c1*t_cur
__global__ __launch_bounds__(256) void cheb_first_kernel(const int* __restrict__ qy,
                                                         const __half* __restrict__ sy,
                                                         int* __restrict__ qt,
                                                         __half* __restrict__ st,
                                                         __half* __restrict__ outb,
                                                         int layer) {
    int lane = threadIdx.x & 31;
    int half_id = lane >> 4;
    int sub = lane & 15;
    int row = blockIdx.x * 16 + ((threadIdx.x >> 5) << 1) + half_id;
    if (row >= NN) return;
    unsigned mask = 0xFFFFu << (half_id << 4);
    int s = g_rowptr[row], e = g_rowptr[row + 1];
    float4 acc = prop_row4_q(qy, sy, s, e, sub, mask);
    float c0 = g_coeff[layer][0], c1 = g_coeff[layer][1];
    size_t idx = (size_t)row * 16 + sub;
    float4 yv = dequant4(qy[idx], __half2float(sy[row]));
    quant_store(acc, qt, st, row, sub, mask);
    ((int2*)outb)[idx] = pack4h(c0 * yv.x + c1 * acc.x, c0 * yv.y + c1 * acc.y,
                                c0 * yv.z + c1 * acc.z, c0 * yv.w + c1 * acc.w);
}

// step k: t_next = 2*L~ t_cur - t_prev ; out += c_k * t_next
__global__ __launch_bounds__(256) void cheb_step_kernel(const int* __restrict__ qc,
                                                        const __half* __restrict__ sc,
                                                        const int* __restrict__ qp,
                                                        const __half* __restrict__ sp,
                                                        int* __restrict__ qn,
                                                        __half* __restrict__ sn,
                                                        __half* __restrict__ outb,
                                                        int layer, int k) {
    int lane = threadIdx.x & 31;
    int half_id = lane >> 4;
    int sub = lane & 15;
    int row = blockIdx.x * 16 + ((threadIdx.x >> 5) << 1) + half_id;
    if (row >= NN) return;
    unsigned mask = 0xFFFFu << (half_id << 4);
    int s = g_rowptr[row], e = g_rowptr[row + 1];
    float4 acc = prop_row4_q(qc, sc, s, e, sub, mask);
    size_t idx = (size_t)row * 16 + sub;
    float4 p = dequant4(qp[idx], __half2float(sp[row]));
    float4 tn = make_float4(2.f * acc.x - p.x, 2.f * acc.y - p.y,
                            2.f * acc.z - p.z, 2.f * acc.w - p.w);
    quant_store(tn, qn, sn, row, sub, mask);
    float ck = g_coeff[layer][k];
    float4 o = unpack4h(((int2*)outb)[idx]);
    ((int2*)outb)[idx] = pack4h(o.x + ck * tn.x, o.y + ck * tn.y,
                                o.z + ck * tn.z, o.w + ck * tn.w);
}

// last step: h_out = relu(out + c_k*(2*L~ t_cur - t_prev) + bias)  (fp32 output)
__global__ __launch_bounds__(256) void cheb_last_kernel(const int* __restrict__ qc,
                                                        const __half* __restrict__ sc,
                                                        const int* __restrict__ qp,
                                                        const __half* __restrict__ sp,
                                                        const __half* __restrict__ outb,
                                                        const float* __restrict__ bias,
                                                        float* __restrict__ hout,
                                                        int layer, int k) {
    int lane = threadIdx.x & 31;
    int half_id = lane >> 4;
    int sub = lane & 15;
    int row = blockIdx.x * 16 + ((threadIdx.x >> 5) << 1) + half_id;
    if (row >= NN) return;
    unsigned mask = 0xFFFFu << (half_id << 4);
    int s = g_rowptr[row], e = g_rowptr[row + 1];
    float4 acc = prop_row4_q(qc, sc, s, e, sub, mask);
    size_t idx = (size_t)row * 16 + sub;
    float4 p = dequant4(qp[idx], __half2float(sp[row]));
    float4 tn = make_float4(2.f * acc.x - p.x, 2.f * acc.y - p.y,
                            2.f * acc.z - p.z, 2.f * acc.w - p.w);
    float ck = g_coeff[layer][k];
    float4 o = unpack4h(((const int2*)outb)[idx]);
    float4 b = *(const float4*)(bias + sub * 4);
    float4 r;
    r.x = fmaxf(o.x + ck * tn.x + b.x, 0.f);
    r.y = fmaxf(o.y + ck * tn.y + b.y, 0.f);
    r.z = fmaxf(o.z + ck * tn.z + b.z, 0.f);
    r.w = fmaxf(o.w + ck * tn.w + b.w, 0.f);
    *(float4*)(hout + (size_t)row * HID + sub * 4) = r;
}

// ---------------- pool + head + log_softmax ----------------
__global__ __launch_bounds__(256) void pool_head_kernel(const float* __restrict__ h,
                                                        const int* __restrict__ batch,
                                                        const float* __restrict__ lin1w,
                                                        const float* __restrict__ lin1b,
                                                        const float* __restrict__ lin2w,
                                                        const float* __restrict__ lin2b,
                                                        float* __restrict__ out) {
    int g = blockIdx.x;
    int tid = threadIdx.x;
    int lo = 0, hi = NN;
    while (lo < hi) { int m = (lo + hi) >> 1; if (batch[m] < g) lo = m + 1; else hi = m; }
    int start = lo;
    lo = start; hi = NN;
    while (lo < hi) { int m = (lo + hi) >> 1; if (batch[m] < g + 1) lo = m + 1; else hi = m; }
    int end = lo;

    int f = tid & 63, sub = tid >> 6;
    float acc = 0.f;
    for (int i = start + sub; i < end; i += 4) acc += h[(size_t)i * HID + f];
    __shared__ float red[4][64];
    red[sub][f] = acc;
    __syncthreads();
    __shared__ float pooled[64];
    if (tid < 64) {
        float s = red[0][tid] + red[1][tid] + red[2][tid] + red[3][tid];
        float cnt = (float)(end - start);
        pooled[tid] = s / fmaxf(cnt, 1.0f);
    }
    __syncthreads();
    __shared__ float g1[64];
    if (tid < 64) {
        float a = lin1b[tid];
        for (int fk = 0; fk < 64; fk++) a += pooled[fk] * lin1w[fk * 64 + tid];
        g1[tid] = fmaxf(a, 0.f);
    }
    __syncthreads();
    __shared__ float logits[NCLS];
    if (tid < NCLS) {
        float a = lin2b[tid];
        for (int fk = 0; fk < 64; fk++) a += g1[fk] * lin2w[fk * NCLS + tid];
        logits[tid] = a;
    }
    __syncthreads();
    __shared__ float s_lse;
    if (tid == 0) {
        float mx = logits[0];
        for (int c = 1; c < NCLS; c++) mx = fmaxf(mx, logits[c]);
        float s = 0.f;
        for (int c = 0; c < NCLS; c++) s += expf(logits[c] - mx);
        s_lse = mx + logf(s);
    }
    __syncthreads();
    if (tid < NCLS) out[g * NCLS + tid] = logits[tid] - s_lse;
}

// ---------------- host orchestration ----------------
struct QBuf { int* q; __half* s; };

static void spectral_layer(const float* hin, int fin, int layer,
                           const float* W, const float* bias,
                           QBuf b0, QBuf b1, QBuf b2,
                           __half* p_outh, float* hout) {
    const int CHEB_GRID = (NN + 15) / 16;
    if (fin == 128)
        gemm_kernel<128><<<(NN + 63) / 64, 256>>>(hin, W, b0.q, b0.s);
    else
        gemm_kernel<64><<<(NN + 63) / 64, 256>>>(hin, W, b0.q, b0.s);
    cheb_first_kernel<<<CHEB_GRID, 256>>>(b0.q, b0.s, b1.q, b1.s, p_outh, layer);
    QBuf tp = b0, tc = b1, tn = b2;
    for (int k = 2; k <= KORD - 2; k++) {
        cheb_step_kernel<<<CHEB_GRID, 256>>>(tc.q, tc.s, tp.q, tp.s, tn.q, tn.s,
                                             p_outh, layer, k);
        QBuf tmp = tp; tp = tc; tc = tn; tn = tmp;
    }
    cheb_last_kernel<<<CHEB_GRID, 256>>>(tc.q, tc.s, tp.q, tp.s, p_outh, bias,
                                         hout, layer, KORD - 1);
}

extern "C" void kernel_launch(void* const* d_in, const int* in_sizes, int n_in,
                              void* d_out, int out_size) {
    const float* x      = (const float*)d_in[0];
    const int*   ei     = (const int*)d_in[1];
    const int*   batch  = (const int*)d_in[2];
    const float* W1     = (const float*)d_in[3];
    const float* theta1 = (const float*)d_in[4];
    const float* b1     = (const float*)d_in[5];
    const float* Ws     = (const float*)d_in[6];
    const float* thetas = (const float*)d_in[7];
    const float* bs     = (const float*)d_in[8];
    const float* lin1w  = (const float*)d_in[9];
    const float* lin1b  = (const float*)d_in[10];
    const float* lin2w  = (const float*)d_in[11];
    const float* lin2b  = (const float*)d_in[12];
    float* out = (float*)d_out;

    const int* row = ei;
    const int* col = ei + EE;

    void* pv;
    QBuf b0, b1q, b2;
    __half* p_outh; float* p_h;
    cudaGetSymbolAddress(&pv, g_q0);   b0.q  = (int*)pv;
    cudaGetSymbolAddress(&pv, g_q1);   b1q.q = (int*)pv;
    cudaGetSymbolAddress(&pv, g_q2);   b2.q  = (int*)pv;
    cudaGetSymbolAddress(&pv, g_s0);   b0.s  = (__half*)pv;
    cudaGetSymbolAddress(&pv, g_s1);   b1q.s = (__half*)pv;
    cudaGetSymbolAddress(&pv, g_s2);   b2.s  = (__half*)pv;
    cudaGetSymbolAddress(&pv, g_outh); p_outh = (__half*)pv;
    cudaGetSymbolAddress(&pv, g_h);    p_h   = (float*)pv;

    // ---- CSR build ----
    init_kernel<<<(NN + 255) / 256, 256>>>();
    count_deg_kernel<<<(EE + 255) / 256, 256>>>(row);
    scan_kernel<<<1, 1024>>>(theta1, thetas);
    scatter_kernel<<<(EE + 255) / 256, 256>>>(row, col);

    // ---- 3 spectral layers ----
    spectral_layer(x,   128, 0, W1,           b1,       b0, b1q, b2, p_outh, p_h);
    spectral_layer(p_h,  64, 1, Ws,           bs,       b0, b1q, b2, p_outh, p_h);
    spectral_layer(p_h,  64, 2, Ws + 64 * 64, bs + HID, b0, b1q, b2, p_outh, p_h);

    // ---- pool + head ----
    pool_head_kernel<<<NGRAPH, 256>>>(p_h, batch, lin1w, lin1b, lin2w, lin2b, out);
}

// round 6
// speedup vs baseline: 1.6546x; 1.6546x over previous
#include <cuda_runtime.h>
#include <cuda_fp16.h>
#include <math.h>

#define NN 100000
#define EE 1600000
#define EPAD (EE + 8 * NN)
#define HID 64
#define KORD 14
#define HEADS 8
#define NGRAPH 128
#define NCLS 10

// ---------------- scratch (device globals; no runtime alloc) ----------------
__device__ __half g_yh  [NN * HID];
__device__ __half g_t1h [NN * HID];
__device__ __half g_t2h [NN * HID];
__device__ __half g_outh[NN * HID];
__device__ float  g_h   [NN * HID];
__device__ int    g_deg[NN];
__device__ float  g_dinv[NN];
__device__ int    g_rowptr[NN + 1];   // PADDED prefix (multiples of 8 per row)
__device__ int    g_cursor[NN];
__device__ int2   g_edge[EPAD];       // {col, float_bits(weight)}, zero-weight padding
__device__ float  g_coeff[3][KORD];

// ---------------- init: zero deg + cursor ----------------
__global__ void init_kernel() {
    int i = blockIdx.x * blockDim.x + threadIdx.x;
    if (i < NN) { g_deg[i] = 0; g_cursor[i] = 0; }
}

__global__ void count_deg_kernel(const int* __restrict__ row) {
    int e = blockIdx.x * blockDim.x + threadIdx.x;
    if (e < EE) atomicAdd(&g_deg[row[e]], 1);
}

// scan (padded degrees) + dinv + coeff fused (single block)
__global__ void scan_kernel(const float* __restrict__ theta1,
                            const float* __restrict__ thetas) {
    __shared__ int sums[1024];
    const int T = 1024;
    int tid = threadIdx.x;

    if (tid < 3 * KORD) {
        int layer = tid / KORD, k = tid % KORD;
        const float* th = (layer == 0) ? theta1 : thetas + (layer - 1) * HEADS * KORD;
        float s = 0.f;
        for (int h = 0; h < HEADS; h++) s += th[h * KORD + k];
        g_coeff[layer][k] = s * (1.0f / HEADS);
    }

    int per = (NN + T - 1) / T;
    int start = tid * per;
    int end = start + per; if (end > NN) end = NN;
    int local = 0;
    for (int i = start; i < end; i++) local += (g_deg[i] + 7) & ~7;
    sums[tid] = local;
    __syncthreads();
    for (int off = 1; off < T; off <<= 1) {
        int t = (tid >= off) ? sums[tid - off] : 0;
        __syncthreads();
        sums[tid] += t;
        __syncthreads();
    }
    int excl = sums[tid] - local;
    int run = excl;
    for (int i = start; i < end; i++) {
        int d = g_deg[i];
        g_rowptr[i] = run; run += (d + 7) & ~7;
        g_dinv[i] = rsqrtf(fmaxf((float)d, 1.0f));
    }
    if (tid == T - 1) g_rowptr[NN] = run;
}

__global__ void scatter_kernel(const int* __restrict__ row, const int* __restrict__ col) {
    int e = blockIdx.x * blockDim.x + threadIdx.x;
    if (e < EE) {
        int r = row[e], c = col[e];
        int pos = g_rowptr[r] + atomicAdd(&g_cursor[r], 1);
        float w = -g_dinv[r] * g_dinv[c];
        g_edge[pos] = make_int2(c, __float_as_int(w));
    }
}

// fill padding slots with {col=0, w=0}
__global__ void pad_fill_kernel() {
    int r = blockIdx.x * blockDim.x + threadIdx.x;
    if (r < NN) {
        int s = g_rowptr[r] + g_deg[r];
        int e = g_rowptr[r + 1];
        for (int i = s; i < e; i++) g_edge[i] = make_int2(0, 0);
    }
}

// ---------------- GEMM: Yh[N][64] = A[N][FIN] @ W[FIN][64]  (half output) ----------------
template <int FIN>
__global__ __launch_bounds__(256) void gemm_kernel(const float* __restrict__ A,
                                                   const float* __restrict__ W,
                                                   __half* __restrict__ Yh) {
    __shared__ float As[64][68];
    __shared__ float Ws[64][64];
    int rowbase = blockIdx.x * 64;
    int tid = threadIdx.x;
    int tx = tid & 15;
    int ty = tid >> 4;
    float acc[4][4];
#pragma unroll
    for (int i = 0; i < 4; i++)
#pragma unroll
        for (int j = 0; j < 4; j++) acc[i][j] = 0.f;

    for (int kk = 0; kk < FIN; kk += 64) {
#pragma unroll
        for (int j = 0; j < 4; j++) {
            int idx = tid + j * 256;
            int r = idx >> 4;
            int kq = idx & 15;
            float4 v = make_float4(0.f, 0.f, 0.f, 0.f);
            int gr = rowbase + r;
            if (gr < NN) v = *(const float4*)(A + (size_t)gr * FIN + kk + kq * 4);
            As[kq * 4 + 0][r] = v.x;
            As[kq * 4 + 1][r] = v.y;
            As[kq * 4 + 2][r] = v.z;
            As[kq * 4 + 3][r] = v.w;
        }
#pragma unroll
        for (int j = 0; j < 4; j++) {
            int idx = tid + j * 256;
            int k = idx >> 4;
            int fq = idx & 15;
            *(float4*)&Ws[k][fq * 4] = *(const float4*)(W + (size_t)(kk + k) * 64 + fq * 4);
        }
        __syncthreads();
#pragma unroll
        for (int k = 0; k < 64; k++) {
            float4 a = *(const float4*)&As[k][ty * 4];
            float4 b = *(const float4*)&Ws[k][tx * 4];
            float ar[4] = {a.x, a.y, a.z, a.w};
            float br[4] = {b.x, b.y, b.z, b.w};
#pragma unroll
            for (int i = 0; i < 4; i++)
#pragma unroll
                for (int j = 0; j < 4; j++) acc[i][j] += ar[i] * br[j];
        }
        __syncthreads();
    }
#pragma unroll
    for (int i = 0; i < 4; i++) {
        int r = rowbase + ty * 4 + i;
        if (r < NN) {
            __half2* dst = (__half2*)(Yh + (size_t)r * HID + tx * 4);
            dst[0] = __floats2half2_rn(acc[i][0], acc[i][1]);
            dst[1] = __floats2half2_rn(acc[i][2], acc[i][3]);
        }
    }
}

// ---------------- Chebyshev propagation: 8-lane group per row, 8 features/lane ----------------
// Branch-free 8-edge chunks (CSR is padded to multiples of 8 with zero-weight edges).
__device__ __forceinline__ void prop_row8(const int4* __restrict__ t,
                                          int st, int en, int sub, unsigned mask,
                                          float* __restrict__ acc) {
    const int4* tp = t + sub;
#pragma unroll
    for (int i = 0; i < 8; i++) acc[i] = 0.f;
    for (int base = st; base < en; base += 8) {
        int2 ew = __ldg(&g_edge[base + sub]);
        int4 raw[8];
#pragma unroll
        for (int j = 0; j < 8; j++) {
            int cj = __shfl_sync(mask, ew.x, j, 8);
            raw[j] = __ldg(&tp[(size_t)cj * 8]);
        }
#pragma unroll
        for (int j = 0; j < 8; j++) {
            float wj = __int_as_float(__shfl_sync(mask, ew.y, j, 8));
            const __half2* h = (const __half2*)&raw[j];
            float2 f0 = __half22float2(h[0]);
            float2 f1 = __half22float2(h[1]);
            float2 f2 = __half22float2(h[2]);
            float2 f3 = __half22float2(h[3]);
            acc[0] += wj * f0.x; acc[1] += wj * f0.y;
            acc[2] += wj * f1.x; acc[3] += wj * f1.y;
            acc[4] += wj * f2.x; acc[5] += wj * f2.y;
            acc[6] += wj * f3.x; acc[7] += wj * f3.y;
        }
    }
}

__device__ __forceinline__ int4 pack8(const float* v) {
    __half2 h0 = __floats2half2_rn(v[0], v[1]);
    __half2 h1 = __floats2half2_rn(v[2], v[3]);
    __half2 h2 = __floats2half2_rn(v[4], v[5]);
    __half2 h3 = __floats2half2_rn(v[6], v[7]);
    int4 r;
    r.x = *(int*)&h0; r.y = *(int*)&h1;
    r.z = *(int*)&h2; r.w = *(int*)&h3;
    return r;
}

__device__ __forceinline__ void unpack8(int4 raw, float* v) {
    const __half2* h = (const __half2*)&raw;
    float2 f0 = __half22float2(h[0]);
    float2 f1 = __half22float2(h[1]);
    float2 f2 = __half22float2(h[2]);
    float2 f3 = __half22float2(h[3]);
    v[0] = f0.x; v[1] = f0.y; v[2] = f1.x; v[3] = f1.y;
    v[4] = f2.x; v[5] = f2.y; v[6] = f3.x; v[7] = f3.y;
}

// first: t_cur = L~ y ; out = c0*y + c1*t_cur
__global__ __launch_bounds__(256) void cheb_first_kernel(const __half* __restrict__ yh,
                                                         __half* __restrict__ tcur,
                                                         __half* __restrict__ outb,
                                                         int layer) {
    int lane = threadIdx.x & 31;
    int sub = lane & 7;
    int row = blockIdx.x * 32 + (threadIdx.x >> 3);
    if (row >= NN) return;
    unsigned mask = 0xFFu << (lane & 24);
    int s = g_rowptr[row], e = g_rowptr[row + 1];
    float acc[8];
    prop_row8((const int4*)yh, s, e, sub, mask, acc);
    float c0 = g_coeff[layer][0], c1 = g_coeff[layer][1];
    size_t idx = (size_t)row * 8 + sub;
    float yv[8];
    unpack8(((const int4*)yh)[idx], yv);
    ((int4*)tcur)[idx] = pack8(acc);
    float ov[8];
#pragma unroll
    for (int i = 0; i < 8; i++) ov[i] = c0 * yv[i] + c1 * acc[i];
    ((int4*)outb)[idx] = pack8(ov);
}

// step k: t_next = 2*L~ t_cur - t_prev ; out += c_k * t_next
__global__ __launch_bounds__(256) void cheb_step_kernel(const __half* __restrict__ tcur,
                                                        const __half* __restrict__ tprev,
                                                        __half* __restrict__ tnext,
                                                        __half* __restrict__ outb,
                                                        int layer, int k) {
    int lane = threadIdx.x & 31;
    int sub = lane & 7;
    int row = blockIdx.x * 32 + (threadIdx.x >> 3);
    if (row >= NN) return;
    unsigned mask = 0xFFu << (lane & 24);
    int s = g_rowptr[row], e = g_rowptr[row + 1];
    float acc[8];
    prop_row8((const int4*)tcur, s, e, sub, mask, acc);
    size_t idx = (size_t)row * 8 + sub;
    float p[8], tn[8], o[8];
    unpack8(((const int4*)tprev)[idx], p);
#pragma unroll
    for (int i = 0; i < 8; i++) tn[i] = 2.f * acc[i] - p[i];
    ((int4*)tnext)[idx] = pack8(tn);
    float ck = g_coeff[layer][k];
    unpack8(((int4*)outb)[idx], o);
#pragma unroll
    for (int i = 0; i < 8; i++) o[i] += ck * tn[i];
    ((int4*)outb)[idx] = pack8(o);
}

// last step: h_out = relu(out + c_k*(2*L~ t_cur - t_prev) + bias)  (fp32 output)
__global__ __launch_bounds__(256) void cheb_last_kernel(const __half* __restrict__ tcur,
                                                        const __half* __restrict__ tprev,
                                                        const __half* __restrict__ outb,
                                                        const float* __restrict__ bias,
                                                        float* __restrict__ hout,
                                                        int layer, int k) {
    int lane = threadIdx.x & 31;
    int sub = lane & 7;
    int row = blockIdx.x * 32 + (threadIdx.x >> 3);
    if (row >= NN) return;
    unsigned mask = 0xFFu << (lane & 24);
    int s = g_rowptr[row], e = g_rowptr[row + 1];
    float acc[8];
    prop_row8((const int4*)tcur, s, e, sub, mask, acc);
    size_t idx = (size_t)row * 8 + sub;
    float p[8], o[8];
    unpack8(((const int4*)tprev)[idx], p);
    unpack8(((const int4*)outb)[idx], o);
    float ck = g_coeff[layer][k];
    float4 b0 = *(const float4*)(bias + sub * 8);
    float4 b1 = *(const float4*)(bias + sub * 8 + 4);
    float bb[8] = {b0.x, b0.y, b0.z, b0.w, b1.x, b1.y, b1.z, b1.w};
    float r[8];
#pragma unroll
    for (int i = 0; i < 8; i++) {
        float tni = 2.f * acc[i] - p[i];
        r[i] = fmaxf(o[i] + ck * tni + bb[i], 0.f);
    }
    float* dst = hout + (size_t)row * HID + sub * 8;
    *(float4*)dst = make_float4(r[0], r[1], r[2], r[3]);
    *(float4*)(dst + 4) = make_float4(r[4], r[5], r[6], r[7]);
}

// ---------------- pool + head + log_softmax ----------------
__global__ __launch_bounds__(256) void pool_head_kernel(const float* __restrict__ h,
                                                        const int* __restrict__ batch,
                                                        const float* __restrict__ lin1w,
                                                        const float* __restrict__ lin1b,
                                                        const float* __restrict__ lin2w,
                                                        const float* __restrict__ lin2b,
                                                        float* __restrict__ out) {
    int g = blockIdx.x;
    int tid = threadIdx.x;
    int lo = 0, hi = NN;
    while (lo < hi) { int m = (lo + hi) >> 1; if (batch[m] < g) lo = m + 1; else hi = m; }
    int start = lo;
    lo = start; hi = NN;
    while (lo < hi) { int m = (lo + hi) >> 1; if (batch[m] < g + 1) lo = m + 1; else hi = m; }
    int end = lo;

    int f = tid & 63, sub = tid >> 6;
    float acc = 0.f;
    for (int i = start + sub; i < end; i += 4) acc += h[(size_t)i * HID + f];
    __shared__ float red[4][64];
    red[sub][f] = acc;
    __syncthreads();
    __shared__ float pooled[64];
    if (tid < 64) {
        float s = red[0][tid] + red[1][tid] + red[2][tid] + red[3][tid];
        float cnt = (float)(end - start);
        pooled[tid] = s / fmaxf(cnt, 1.0f);
    }
    __syncthreads();
    __shared__ float g1[64];
    if (tid < 64) {
        float a = lin1b[tid];
        for (int fk = 0; fk < 64; fk++) a += pooled[fk] * lin1w[fk * 64 + tid];
        g1[tid] = fmaxf(a, 0.f);
    }
    __syncthreads();
    __shared__ float logits[NCLS];
    if (tid < NCLS) {
        float a = lin2b[tid];
        for (int fk = 0; fk < 64; fk++) a += g1[fk] * lin2w[fk * NCLS + tid];
        logits[tid] = a;
    }
    __syncthreads();
    __shared__ float s_lse;
    if (tid == 0) {
        float mx = logits[0];
        for (int c = 1; c < NCLS; c++) mx = fmaxf(mx, logits[c]);
        float s = 0.f;
        for (int c = 0; c < NCLS; c++) s += expf(logits[c] - mx);
        s_lse = mx + logf(s);
    }
    __syncthreads();
    if (tid < NCLS) out[g * NCLS + tid] = logits[tid] - s_lse;
}

// ---------------- host orchestration ----------------
static void spectral_layer(const float* hin, int fin, int layer,
                           const float* W, const float* bias,
                           __half* p_yh, __half* p_t1h, __half* p_t2h,
                           __half* p_outh, float* hout) {
    const int CHEB_GRID = (NN + 31) / 32;
    if (fin == 128)
        gemm_kernel<128><<<(NN + 63) / 64, 256>>>(hin, W, p_yh);
    else
        gemm_kernel<64><<<(NN + 63) / 64, 256>>>(hin, W, p_yh);
    cheb_first_kernel<<<CHEB_GRID, 256>>>(p_yh, p_t1h, p_outh, layer);
    __half* tp = p_yh; __half* tc = p_t1h; __half* tn = p_t2h;
    for (int k = 2; k <= KORD - 2; k++) {
        cheb_step_kernel<<<CHEB_GRID, 256>>>(tc, tp, tn, p_outh, layer, k);
        __half* tmp = tp; tp = tc; tc = tn; tn = tmp;
    }
    cheb_last_kernel<<<CHEB_GRID, 256>>>(tc, tp, p_outh, bias, hout, layer, KORD - 1);
}

extern "C" void kernel_launch(void* const* d_in, const int* in_sizes, int n_in,
                              void* d_out, int out_size) {
    const float* x      = (const float*)d_in[0];
    const int*   ei     = (const int*)d_in[1];
    const int*   batch  = (const int*)d_in[2];
    const float* W1     = (const float*)d_in[3];
    const float* theta1 = (const float*)d_in[4];
    const float* b1     = (const float*)d_in[5];
    const float* Ws     = (const float*)d_in[6];
    const float* thetas = (const float*)d_in[7];
    const float* bs     = (const float*)d_in[8];
    const float* lin1w  = (const float*)d_in[9];
    const float* lin1b  = (const float*)d_in[10];
    const float* lin2w  = (const float*)d_in[11];
    const float* lin2b  = (const float*)d_in[12];
    float* out = (float*)d_out;

    const int* row = ei;
    const int* col = ei + EE;

    void* pv;
    __half *p_yh, *p_t1h, *p_t2h, *p_outh;
    float* p_h;
    cudaGetSymbolAddress(&pv, g_yh);   p_yh  = (__half*)pv;
    cudaGetSymbolAddress(&pv, g_t1h);  p_t1h = (__half*)pv;
    cudaGetSymbolAddress(&pv, g_t2h);  p_t2h = (__half*)pv;
    cudaGetSymbolAddress(&pv, g_outh); p_outh = (__half*)pv;
    cudaGetSymbolAddress(&pv, g_h);    p_h   = (float*)pv;

    // ---- padded CSR build ----
    init_kernel<<<(NN + 255) / 256, 256>>>();
    count_deg_kernel<<<(EE + 255) / 256, 256>>>(row);
    scan_kernel<<<1, 1024>>>(theta1, thetas);
    scatter_kernel<<<(EE + 255) / 256, 256>>>(row, col);
    pad_fill_kernel<<<(NN + 255) / 256, 256>>>();

    // ---- 3 spectral layers ----
    spectral_layer(x,   128, 0, W1,           b1,       p_yh, p_t1h, p_t2h, p_outh, p_h);
    spectral_layer(p_h,  64, 1, Ws,           bs,       p_yh, p_t1h, p_t2h, p_outh, p_h);
    spectral_layer(p_h,  64, 2, Ws + 64 * 64, bs + HID, p_yh, p_t1h, p_t2h, p_outh, p_h);

    // ---- pool + head ----
    pool_head_kernel<<<NGRAPH, 256>>>(p_h, batch, lin1w, lin1b, lin2w, lin2b, out);
}